// round 4
// baseline (speedup 1.0000x reference)
#include <cuda_runtime.h>
#include <cuda_bf16.h>

// Grouped submanifold sparse conv, N=400000, C_IN=C_OUT=64, GROUPS=4, K=27.
// R4: flat body-stream with depth-3 software pipeline across union-k
// boundaries. Bodies = (voxel j, offset k) pairs; loads for body i+2 are in
// flight while body i computes. Dynamic-j accumulation via switch into static
// regs; neighbor index via uniform LDG from the L1-hot nb row; weights
// register-cached per k (reloaded on k change only).

#define GROUPS 4
#define KOFF   27
#define CPG    16
#define WK     (CPG * CPG)      // 256 floats per (g,k)
#define WG_RAW (KOFF * WK)      // 6912 floats per group
#define PG     (WG_RAW + 16)    // padded group stride
#define SMEM_BYTES (GROUPS * PG * 4)
#define VPW 8
#define FULL 0xffffffffu

__global__ __launch_bounds__(256, 2)
void subm_conv_r4(const float* __restrict__ feat,
                  const float* __restrict__ weight,
                  const float* __restrict__ bias,
                  const int* __restrict__ nb,
                  float* __restrict__ out,
                  int N, int iters_per_warp, int total_iters)
{
    extern __shared__ float sw[];
    for (int i = threadIdx.x; i < GROUPS * WG_RAW; i += blockDim.x) {
        int g = i / WG_RAW;
        sw[g * PG + (i - g * WG_RAW)] = weight[i];
    }
    __syncthreads();

    const int lane = threadIdx.x & 31;
    const int gwarp = (blockIdx.x * blockDim.x + threadIdx.x) >> 5;
    const int g    = lane >> 3;
    const int co0  = (lane & 7) * 2;
    const float bx = bias[2 * lane];
    const float by = bias[2 * lane + 1];
    const float* wgbase = sw + g * PG + co0;

    int it0 = gwarp * iters_per_warp;
    int it1 = it0 + iters_per_warp;
    if (it1 > total_iters) it1 = total_iters;

    for (int it = it0; it < it1; ++it) {
        const int vb = it * VPW;
        const int* nbrow = nb + (size_t)vb * KOFF;

        // Activity byte per lane: bit j = (voxel vb+j active at offset 'lane').
        unsigned am = 0;
        #pragma unroll
        for (int j = 0; j < VPW; ++j) {
            int v = vb + j;
            int id = (lane < KOFF && v < N) ? nbrow[j * KOFF + lane] : -1;
            am |= (id >= 0 ? 1u : 0u) << j;
        }
        unsigned uni = __ballot_sync(FULL, am != 0);

        float2 a0 = {bx, by}, a1 = {bx, by}, a2 = {bx, by}, a3 = {bx, by};
        float2 a4 = {bx, by}, a5 = {bx, by}, a6 = {bx, by}, a7 = {bx, by};

        // ---- body-stream cursor (all warp-uniform control) ----
        unsigned uniL = uni, jmL = 0;
        int kL = 0;
        auto advance = [&](int& jo, int& ko) -> bool {
            if (jmL == 0) {
                if (uniL == 0) return false;
                kL = __ffs(uniL) - 1; uniL &= uniL - 1;
                jmL = __shfl_sync(FULL, am, kL);   // jm != 0 guaranteed
            }
            jo = __ffs(jmL) - 1; jmL &= jmL - 1; ko = kL;
            return true;
        };

        auto loadfr = [&](float4* fr, int j, int k) {
            int ni = nbrow[j * KOFF + k];          // uniform LDG, L1-hot row
            const float4* fp = (const float4*)feat + (size_t)ni * 16 + g * 4;
            fr[0] = fp[0]; fr[1] = fp[1]; fr[2] = fp[2]; fr[3] = fp[3];
        };

        float2 w[16];
        int kcur = -1;
        auto consume = [&](const float4* fr, int j, int k) {
            if (k != kcur) {                        // ~once per 2.15 bodies
                kcur = k;
                const float2* wp = (const float2*)(wgbase + k * WK);
                #pragma unroll
                for (int i = 0; i < 16; ++i) w[i] = wp[i * 8];
            }
            // 4 interleaved FFMA chains (16-deep each) to break acc latency.
            float ax  = fr[0].x * w[0].x,  ay  = fr[0].x * w[0].y;
            float ax2 = fr[0].y * w[1].x,  ay2 = fr[0].y * w[1].y;
            ax  += fr[0].z * w[2].x;   ay  += fr[0].z * w[2].y;
            ax2 += fr[0].w * w[3].x;   ay2 += fr[0].w * w[3].y;
            ax  += fr[1].x * w[4].x;   ay  += fr[1].x * w[4].y;
            ax2 += fr[1].y * w[5].x;   ay2 += fr[1].y * w[5].y;
            ax  += fr[1].z * w[6].x;   ay  += fr[1].z * w[6].y;
            ax2 += fr[1].w * w[7].x;   ay2 += fr[1].w * w[7].y;
            ax  += fr[2].x * w[8].x;   ay  += fr[2].x * w[8].y;
            ax2 += fr[2].y * w[9].x;   ay2 += fr[2].y * w[9].y;
            ax  += fr[2].z * w[10].x;  ay  += fr[2].z * w[10].y;
            ax2 += fr[2].w * w[11].x;  ay2 += fr[2].w * w[11].y;
            ax  += fr[3].x * w[12].x;  ay  += fr[3].x * w[12].y;
            ax2 += fr[3].y * w[13].x;  ay2 += fr[3].y * w[13].y;
            ax  += fr[3].z * w[14].x;  ay  += fr[3].z * w[14].y;
            ax2 += fr[3].w * w[15].x;  ay2 += fr[3].w * w[15].y;
            ax += ax2; ay += ay2;
            switch (j) {                            // warp-uniform, 2 adds/case
                case 0: a0.x += ax; a0.y += ay; break;
                case 1: a1.x += ax; a1.y += ay; break;
                case 2: a2.x += ax; a2.y += ay; break;
                case 3: a3.x += ax; a3.y += ay; break;
                case 4: a4.x += ax; a4.y += ay; break;
                case 5: a5.x += ax; a5.y += ay; break;
                case 6: a6.x += ax; a6.y += ay; break;
                default: a7.x += ax; a7.y += ay; break;
            }
        };

        // ---- depth-3 rotating pipeline over the body stream ----
        float4 frA[4], frB[4], frC[4];
        int jA, kA, jB, kB, jC, kC;
        bool vA = advance(jA, kA); if (vA) loadfr(frA, jA, kA);
        bool vB = advance(jB, kB); if (vB) loadfr(frB, jB, kB);
        bool vC = advance(jC, kC); if (vC) loadfr(frC, jC, kC);
        while (vA) {
            consume(frA, jA, kA);
            vA = advance(jA, kA); if (vA) loadfr(frA, jA, kA);
            if (!vB) break;
            consume(frB, jB, kB);
            vB = advance(jB, kB); if (vB) loadfr(frB, jB, kB);
            if (!vC) break;
            consume(frC, jC, kC);
            vC = advance(jC, kC); if (vC) loadfr(frC, jC, kC);
        }

        // ---- epilogue: store 8 voxels x 64 channels ----
        float2* opb = (float2*)(out + (size_t)vb * 64);
        if (vb + 7 < N) {
            opb[0 * 32 + lane] = a0;  opb[1 * 32 + lane] = a1;
            opb[2 * 32 + lane] = a2;  opb[3 * 32 + lane] = a3;
            opb[4 * 32 + lane] = a4;  opb[5 * 32 + lane] = a5;
            opb[6 * 32 + lane] = a6;  opb[7 * 32 + lane] = a7;
        } else {
            if (vb + 0 < N) opb[0 * 32 + lane] = a0;
            if (vb + 1 < N) opb[1 * 32 + lane] = a1;
            if (vb + 2 < N) opb[2 * 32 + lane] = a2;
            if (vb + 3 < N) opb[3 * 32 + lane] = a3;
            if (vb + 4 < N) opb[4 * 32 + lane] = a4;
            if (vb + 5 < N) opb[5 * 32 + lane] = a5;
            if (vb + 6 < N) opb[6 * 32 + lane] = a6;
            if (vb + 7 < N) opb[7 * 32 + lane] = a7;
        }
    }
}

extern "C" void kernel_launch(void* const* d_in, const int* in_sizes, int n_in,
                              void* d_out, int out_size)
{
    const float* feat   = (const float*)d_in[0];  // [N, 64]
    const float* weight = (const float*)d_in[1];  // [4, 27, 16, 16]
    const float* bias   = (const float*)d_in[2];  // [64]
    const int*   nb     = (const int*)d_in[3];    // [N, 27]
    float* out = (float*)d_out;

    int N = in_sizes[0] / 64;

    // Idempotent, enqueues no work; safe under graph capture.
    cudaFuncSetAttribute(subm_conv_r4,
                         cudaFuncAttributeMaxDynamicSharedMemorySize, SMEM_BYTES);

    const int blocks = 304;     // 2 CTAs/SM (110.8KB smem x2 fits 228KB)
    const int threads = 256;
    const int warps = blocks * (threads / 32);
    int total_iters = (N + VPW - 1) / VPW;
    int iters_per_warp = (total_iters + warps - 1) / warps;

    subm_conv_r4<<<blocks, threads, SMEM_BYTES>>>(feat, weight, bias, nb,
                                                  out, N, iters_per_warp,
                                                  total_iters);
    (void)n_in; (void)out_size;
}